// round 16
// baseline (speedup 1.0000x reference)
#include <cuda_runtime.h>
#include <cuda_fp16.h>
#include <cstdint>
#include <math.h>

#define BSZ 16384
#define TN  10
#define IN_ 184
#define HN  128
#define WST 384          // weight-cat row stride (fp16 elems)
#define XPS (TN * 1024)  // xproj row stride per batch (fp32 elems)

// ------------------------- scratch (__device__ globals) -------------------------
__device__ __half g_x1[(size_t)BSZ * TN * 192];
__device__ __half g_o1[(size_t)BSZ * TN * 256];
__device__ __half g_o2[(size_t)BSZ * TN * 256];
__device__ __half g_w[(size_t)4 * 512 * WST];
__device__ float g_xp[(size_t)BSZ * TN * 1024];   // [bt][dir*512 + 4*u+g]
__device__ float g_cf[(size_t)BSZ * HN];
__device__ float g_cb[(size_t)BSZ * HN];
__device__ float g_pooled[(size_t)BSZ * 512];

// ------------------------- small helpers -------------------------
__device__ __forceinline__ uint32_t smem_u32(const void* p) {
    uint32_t a;
    asm("{ .reg .u64 t; cvta.to.shared.u64 t, %1; cvt.u32.u64 %0, t; }" : "=r"(a) : "l"(p));
    return a;
}
__device__ __forceinline__ void ldsm_x4(uint32_t& r0, uint32_t& r1, uint32_t& r2, uint32_t& r3, uint32_t addr) {
    asm volatile("ldmatrix.sync.aligned.m8n8.x4.shared.b16 {%0,%1,%2,%3}, [%4];"
                 : "=r"(r0), "=r"(r1), "=r"(r2), "=r"(r3) : "r"(addr));
}
__device__ __forceinline__ void mma16816(float* d, const uint32_t* a, const uint32_t* b) {
    asm volatile("mma.sync.aligned.m16n8k16.row.col.f32.f16.f16.f32 "
                 "{%0,%1,%2,%3}, {%4,%5,%6,%7}, {%8,%9}, {%0,%1,%2,%3};"
                 : "+f"(d[0]), "+f"(d[1]), "+f"(d[2]), "+f"(d[3])
                 : "r"(a[0]), "r"(a[1]), "r"(a[2]), "r"(a[3]), "r"(b[0]), "r"(b[1]));
}
__device__ __forceinline__ float ftanh(float x) {     // rel err ~1e-6, handles +-inf
    float e = __expf(2.f * x);
    return 1.f - 2.f / (e + 1.f);
}

// ------------------------- conversions -------------------------
__global__ void conv_x_kernel(const float* __restrict__ x, __half* __restrict__ xo) {
    long i = (long)blockIdx.x * blockDim.x + threadIdx.x;
    if (i >= (long)BSZ * TN * 192) return;
    int col = (int)(i % 192);
    long bt = i / 192;
    float v = (col < IN_) ? x[bt * IN_ + col] : 0.f;
    xo[i] = __float2half_rn(v);
}

__global__ void conv_w_kernel(const float* __restrict__ a0, const float* __restrict__ h0,
                              const float* __restrict__ a1, const float* __restrict__ h1,
                              const float* __restrict__ a2, const float* __restrict__ h2,
                              const float* __restrict__ a3, const float* __restrict__ h3,
                              __half* __restrict__ w) {
    long i = (long)blockIdx.x * blockDim.x + threadIdx.x;
    if (i >= (long)4 * 512 * WST) return;
    int col = (int)(i % WST);
    int r = (int)((i / WST) % 512);
    int cfg = (int)(i / ((long)512 * WST));
    const float* wih; const float* whh; int kx, hoff;
    switch (cfg) {
        case 0: wih = a0; whh = h0; kx = 184; hoff = 192; break;
        case 1: wih = a1; whh = h1; kx = 184; hoff = 192; break;
        case 2: wih = a2; whh = h2; kx = 256; hoff = 256; break;
        default: wih = a3; whh = h3; kx = 256; hoff = 256; break;
    }
    float v = 0.f;
    if (col < kx)                             v = wih[(long)r * kx + col];
    else if (col >= hoff && col < hoff + 128) v = whh[(long)r * 128 + (col - hoff)];
    w[i] = __float2half_rn(v);
}

// ------------------------- batched x-projection GEMM -------------------------
// xp[bt][n] = sum_k A[bt][k] * Wcat[n][k],  n in [0,1024): dir = n>>9, col-in-dir = 4*u+g.
// Block 128(M) x 128(N), 256 thr = 8 warps (2m x 4n), warp tile 64x32. fp16 mma, fp32 out.
#define GLDA 72
#define G_TA (128 * GLDA)
#define GSMEM ((G_TA + G_TA) * 2)

__global__ __launch_bounds__(256, 2)
void gemm_xp(const __half* __restrict__ A, long lda,
             const __half* __restrict__ wbase,   // layer base: 2 cfgs of [512][WST]
             float* __restrict__ xp, int kchunks)
{
    extern __shared__ char dyn[];
    const uint32_t sb = smem_u32(dyn);
    const uint32_t uA = sb, uW = sb + G_TA * 2;
    __half* sA = (__half*)dyn;
    __half* sW = sA + G_TA;

    const int tid = threadIdx.x, lane = tid & 31, warp = tid >> 5;
    const int wm = warp >> 2, wn = warp & 3;
    const long b0 = (long)blockIdx.x * 128;
    const int n0 = blockIdx.y * 128;
    const __half* wcfg = wbase + (size_t)(n0 >> 9) * 512 * WST;

    float acc[4][4][4];
#pragma unroll
    for (int i = 0; i < 4; ++i)
#pragma unroll
        for (int j = 0; j < 4; ++j)
#pragma unroll
            for (int k = 0; k < 4; ++k) acc[i][j][k] = 0.f;

    const int aRow = (lane & 15), aKo = (lane >> 4) * 8;
    const int bRow = (lane & 7);
    const int bKo  = ((lane >> 3) & 1) * 8;
    const int bNs  = ((lane >> 4) & 1) * 8;

    for (int c = 0; c < kchunks; ++c) {
#pragma unroll
        for (int it = 0; it < 4; ++it) {
            int idx = tid + it * 256;               // 1024 granules
            int row = idx >> 3, gc = idx & 7;
            *(uint4*)(sA + (uint32_t)row * GLDA + gc * 8) =
                *(const uint4*)(A + (b0 + row) * lda + (long)c * 64 + gc * 8);
        }
#pragma unroll
        for (int it = 0; it < 4; ++it) {
            int idx = tid + it * 256;
            int cl2 = idx >> 3, gc = idx & 7;
            int cl = (n0 + cl2) & 511;
            int wr = (cl & 3) * 128 + (cl >> 2);
            *(uint4*)(sW + (uint32_t)cl2 * GLDA + gc * 8) =
                *(const uint4*)(wcfg + (long)wr * WST + (long)c * 64 + gc * 8);
        }
        __syncthreads();
#pragma unroll
        for (int kk = 0; kk < 4; ++kk) {
            uint32_t bw[2][4];
#pragma unroll
            for (int np = 0; np < 2; ++np) {
                const uint32_t boff = ((uint32_t)(wn * 32 + np * 16 + bNs + bRow) * GLDA + kk * 16 + bKo) * 2;
                ldsm_x4(bw[np][0], bw[np][1], bw[np][2], bw[np][3], uW + boff);
            }
            const uint32_t aoff = ((uint32_t)(wm * 64 + aRow) * GLDA + kk * 16 + aKo) * 2;
#pragma unroll
            for (int mi = 0; mi < 4; ++mi) {
                uint32_t a[4];
                ldsm_x4(a[0], a[1], a[2], a[3], uA + aoff + mi * 16 * GLDA * 2);
                mma16816(acc[mi][0], a, bw[0] + 0);
                mma16816(acc[mi][1], a, bw[0] + 2);
                mma16816(acc[mi][2], a, bw[1] + 0);
                mma16816(acc[mi][3], a, bw[1] + 2);
            }
        }
        __syncthreads();
    }

    // store fp32 (raw mma fragment layout)
#pragma unroll
    for (int mi = 0; mi < 4; ++mi) {
        const long r = b0 + wm * 64 + mi * 16 + (lane >> 2);
#pragma unroll
        for (int j = 0; j < 4; ++j) {
            const int cn = n0 + wn * 32 + (j >> 1) * 16 + (j & 1) * 8 + (lane & 3) * 2;
            *(float2*)&xp[r * 1024 + cn]       = make_float2(acc[mi][j][0], acc[mi][j][1]);
            *(float2*)&xp[(r + 8) * 1024 + cn] = make_float2(acc[mi][j][2], acc[mi][j][3]);
        }
    }
}

// ------------------------- fused HMMA LSTM step (h-part only) -------------------------
// Block 128 batch rows x 64 cols (16 units x 4 gates). 8 warps (2m x 4n), warp tile 64x16.
// acc initialized from xproj (fp32), then 2 K-chunks of h * Whh.
struct DirP {
    const float *xp;                  // xproj base: + t*1024 + dir*512 (row stride XPS)
    const __half *ah;                 // h prev-time base (+dir col); unused if first
    const __half *w;                  // weight-cat cfg [512][WST]
    const float *bih, *bhh;
    float* cbuf;
    __half *o;
    long hstride, ostride;
    int whoff;                        // h-part col offset in weight-cat (192 or 256)
};
struct StepP { DirP d[2]; int first; };

#define LDA 72
#define T_A (128 * LDA)
#define T_W (64 * LDA)
#define SMEM_DYN ((T_A + T_W) * 2 + 512)

__global__ __launch_bounds__(256, 4)
void lstm_mma(StepP sp)
{
    extern __shared__ char dyn[];
    float* sBias = (float*)(dyn + (T_A + T_W) * 2);
    const uint32_t sb = smem_u32(dyn);
    const uint32_t uA = sb, uW = sb + T_A * 2;
    __half* sA = (__half*)dyn;
    __half* sW = sA + T_A;

    const DirP& P = sp.d[blockIdx.z];
    const int first = sp.first;
    const int tid = threadIdx.x, lane = tid & 31, warp = tid >> 5;
    const int wm = warp >> 2, wn = warp & 3;
    const int b0 = blockIdx.x * 128;
    const int n0u = blockIdx.y * 16;

    if (tid < 64) {
        int u = tid >> 2, g = tid & 3;
        int wr = g * 128 + n0u + u;
        sBias[tid] = P.bih[wr] + P.bhh[wr];
    }

    // ---- acc init from xproj (raw mma fragment layout; matches gemm_xp store) ----
    float acc[4][2][4];
#pragma unroll
    for (int mi = 0; mi < 4; ++mi) {
        const long r = b0 + wm * 64 + mi * 16 + (lane >> 2);
#pragma unroll
        for (int ni = 0; ni < 2; ++ni) {
            const int cn = blockIdx.y * 64 + wn * 16 + ni * 8 + (lane & 3) * 2;
            float2 v0 = *(const float2*)&P.xp[r * XPS + cn];
            float2 v1 = *(const float2*)&P.xp[(r + 8) * XPS + cn];
            acc[mi][ni][0] = v0.x; acc[mi][ni][1] = v0.y;
            acc[mi][ni][2] = v1.x; acc[mi][ni][3] = v1.y;
        }
    }

    const int nc = first ? 0 : 2;

    const int aRow = (lane & 15), aKo = (lane >> 4) * 8;
    const int bRow = (lane & 7);
    const int bKo  = ((lane >> 3) & 1) * 8;
    const int bNs  = ((lane >> 4) & 1) * 8;

    for (int c = 0; c < nc; ++c) {
        const long acol = (long)c * 64;
#pragma unroll
        for (int it = 0; it < 4; ++it) {
            int idx = tid + it * 256;
            int row = idx >> 3, gc = idx & 7;
            *(uint4*)(sA + (uint32_t)row * LDA + gc * 8) =
                *(const uint4*)(P.ah + (long)(b0 + row) * P.hstride + acol + gc * 8);
        }
#pragma unroll
        for (int it = 0; it < 2; ++it) {
            int idx = tid + it * 256;
            int cl = idx >> 3, gc = idx & 7;
            int wr = (cl & 3) * 128 + n0u + (cl >> 2);
            *(uint4*)(sW + (uint32_t)cl * LDA + gc * 8) =
                *(const uint4*)(P.w + (long)wr * WST + P.whoff + c * 64 + gc * 8);
        }
        __syncthreads();
#pragma unroll
        for (int kk = 0; kk < 4; ++kk) {
            uint32_t bw[4];
            const uint32_t boff = ((uint32_t)(wn * 16 + bNs + bRow) * LDA + kk * 16 + bKo) * 2;
            ldsm_x4(bw[0], bw[1], bw[2], bw[3], uW + boff);
            const uint32_t aoff = ((uint32_t)(wm * 64 + aRow) * LDA + kk * 16 + aKo) * 2;
#pragma unroll
            for (int mi = 0; mi < 4; ++mi) {
                uint32_t a[4];
                ldsm_x4(a[0], a[1], a[2], a[3], uA + aoff + mi * 16 * LDA * 2);
                mma16816(acc[mi][0], a, bw + 0);
                mma16816(acc[mi][1], a, bw + 2);
            }
        }
        __syncthreads();
    }
    __syncthreads();   // orders sBias for the nc==0 path

    // ---- epilogue ----
    const bool odd = (lane & 1);
    const int rbase = lane >> 2;
    const int usub = (lane >> 1) & 1;
#pragma unroll
    for (int mi = 0; mi < 4; ++mi) {
#pragma unroll
        for (int ni = 0; ni < 2; ++ni) {
            float c0 = acc[mi][ni][0], c1 = acc[mi][ni][1], c2 = acc[mi][ni][2], c3 = acc[mi][ni][3];
            float s0 = __shfl_xor_sync(0xFFFFFFFFu, c0, 1);
            float s1 = __shfl_xor_sync(0xFFFFFFFFu, c1, 1);
            float s2 = __shfl_xor_sync(0xFFFFFFFFu, c2, 1);
            float s3 = __shfl_xor_sync(0xFFFFFFFFu, c3, 1);
            float vi, vf, vg, vo;
            int r;
            if (!odd) { vi = c0; vf = c1; vg = s0; vo = s1; r = rbase; }
            else      { vi = s2; vf = s3; vg = c2; vo = c3; r = rbase + 8; }
            const int ul = wn * 4 + ni * 2 + usub;
            const float4 bb = *(const float4*)&sBias[4 * ul];
            vi += bb.x; vf += bb.y; vg += bb.z; vo += bb.w;
            float ig = 1.f / (1.f + __expf(-vi));
            float fg = 1.f / (1.f + __expf(-vf));
            float gg = ftanh(vg);
            float og = 1.f / (1.f + __expf(-vo));
            const long b = b0 + wm * 64 + mi * 16 + r;
            const int gu = n0u + ul;
            float cp = first ? 0.f : P.cbuf[b * HN + gu];
            float cn = fg * cp + ig * gg;
            P.cbuf[b * HN + gu] = cn;
            float h = og * ftanh(cn);
            P.o[b * P.ostride + gu] = __float2half_rn(h);
        }
    }
}

// ------------------------- temporal max-pool -------------------------
__global__ void pool_kernel(const __half* __restrict__ o2, float* __restrict__ pooled)
{
    long idx = (long)blockIdx.x * blockDim.x + threadIdx.x;
    if (idx >= (long)BSZ * 512) return;
    int b = (int)(idx >> 9);
    int col = (int)(idx & 511);
    int h = col >> 1, p = col & 1;
    long base = ((long)b * TN + p * 5) * 256 + h;
    float m = -1e30f;
#pragma unroll
    for (int s = 0; s < 5; ++s)
        m = fmaxf(m, __half2float(o2[base + (long)s * 256]));
    pooled[idx] = m;
}

// ------------------------- fused FC1(relu)+FC2 -------------------------
__global__ __launch_bounds__(256)
void fc_kernel(const float* __restrict__ pooled,
               const float* __restrict__ w1, const float* __restrict__ b1,
               const float* __restrict__ w2, const float* __restrict__ b2,
               float* __restrict__ outp)
{
    __shared__ float S[64 * 65 + 64 * 64];
    float (*Ws)[65] = (float (*)[65])S;
    float (*Ps)[64] = (float (*)[64])(S + 64 * 65);

    const int tid = threadIdx.x;
    const int b0 = blockIdx.x * 64;
    const int o  = tid & 63;
    const int tg = tid >> 6;

    float acc[16];
#pragma unroll
    for (int r = 0; r < 16; ++r) acc[r] = 0.f;

    for (int kt = 0; kt < 512; kt += 64) {
        for (int e = tid; e < 64 * 64; e += 256) {
            int oo = e >> 6, k = e & 63;
            Ws[k][oo] = w1[(long)oo * 512 + kt + k];
            Ps[oo][k] = pooled[(long)(b0 + oo) * 512 + kt + k];
        }
        __syncthreads();
#pragma unroll 4
        for (int k = 0; k < 64; ++k) {
            float w = Ws[k][o];
#pragma unroll
            for (int r = 0; r < 16; ++r)
                acc[r] = fmaf(Ps[tg * 16 + r][k], w, acc[r]);
        }
        __syncthreads();
    }
    float (*H1)[65] = (float (*)[65])S;
    float bias1 = b1[o];
#pragma unroll
    for (int r = 0; r < 16; ++r)
        H1[tg * 16 + r][o] = fmaxf(acc[r] + bias1, 0.f);
    __syncthreads();
    if (tid < 64) {
        float a2 = b2[0];
#pragma unroll
        for (int oo = 0; oo < 64; ++oo) a2 = fmaf(H1[tid][oo], w2[oo], a2);
        outp[b0 + tid] = a2;
    }
}

// ------------------------- host launcher -------------------------
extern "C" void kernel_launch(void* const* d_in, const int* in_sizes, int n_in,
                              void* d_out, int out_size)
{
    const float* x       = (const float*)d_in[0];
    const float* w_ih1_f = (const float*)d_in[1];
    const float* w_hh1_f = (const float*)d_in[2];
    const float* b_ih1_f = (const float*)d_in[3];
    const float* b_hh1_f = (const float*)d_in[4];
    const float* w_ih1_b = (const float*)d_in[5];
    const float* w_hh1_b = (const float*)d_in[6];
    const float* b_ih1_b = (const float*)d_in[7];
    const float* b_hh1_b = (const float*)d_in[8];
    const float* w_ih2_f = (const float*)d_in[9];
    const float* w_hh2_f = (const float*)d_in[10];
    const float* b_ih2_f = (const float*)d_in[11];
    const float* b_hh2_f = (const float*)d_in[12];
    const float* w_ih2_b = (const float*)d_in[13];
    const float* w_hh2_b = (const float*)d_in[14];
    const float* b_ih2_b = (const float*)d_in[15];
    const float* b_hh2_b = (const float*)d_in[16];
    const float* fc1_w   = (const float*)d_in[17];
    const float* fc1_b   = (const float*)d_in[18];
    const float* fc2_w   = (const float*)d_in[19];
    const float* fc2_b   = (const float*)d_in[20];

    __half *x1, *o1, *o2, *w;
    float *xp, *cf, *cb, *pooled;
    cudaGetSymbolAddress((void**)&x1, g_x1);
    cudaGetSymbolAddress((void**)&o1, g_o1);
    cudaGetSymbolAddress((void**)&o2, g_o2);
    cudaGetSymbolAddress((void**)&w, g_w);
    cudaGetSymbolAddress((void**)&xp, g_xp);
    cudaGetSymbolAddress((void**)&cf, g_cf);
    cudaGetSymbolAddress((void**)&cb, g_cb);
    cudaGetSymbolAddress((void**)&pooled, g_pooled);

    cudaFuncSetAttribute(lstm_mma, cudaFuncAttributeMaxDynamicSharedMemorySize, SMEM_DYN);
    cudaFuncSetAttribute(gemm_xp, cudaFuncAttributeMaxDynamicSharedMemorySize, GSMEM);

    {
        long n = (long)BSZ * TN * 192;
        conv_x_kernel<<<(unsigned)((n + 255) / 256), 256>>>(x, x1);
        long m = (long)4 * 512 * WST;
        conv_w_kernel<<<(unsigned)((m + 255) / 256), 256>>>(
            w_ih1_f, w_hh1_f, w_ih1_b, w_hh1_b, w_ih2_f, w_hh2_f, w_ih2_b, w_hh2_b, w);
    }

    const long WCFG = (long)512 * WST;
    dim3 ggrid(BSZ * TN / 128, 8), gblk(256);
    dim3 sgrid(BSZ / 128, 8, 2), sblk(256);

    // ---- layer 1 ----
    gemm_xp<<<ggrid, gblk, GSMEM>>>(x1, 192, w, xp, 3);
    for (int t = 0; t < TN; ++t) {
        StepP sp;
        sp.first = (t == 0);
        sp.d[0].xp = xp + (long)t * 1024;
        sp.d[0].ah = t ? o1 + (long)(t - 1) * 256 : o1;
        sp.d[0].w = w + 0 * WCFG;
        sp.d[0].bih = b_ih1_f; sp.d[0].bhh = b_hh1_f;
        sp.d[0].cbuf = cf;
        sp.d[0].o = o1 + (long)t * 256;
        sp.d[0].hstride = (long)TN * 256; sp.d[0].ostride = (long)TN * 256;
        sp.d[0].whoff = 192;
        int tt = TN - 1 - t;
        sp.d[1].xp = xp + (long)tt * 1024 + 512;
        sp.d[1].ah = t ? o1 + (long)(tt + 1) * 256 + HN : o1;
        sp.d[1].w = w + 1 * WCFG;
        sp.d[1].bih = b_ih1_b; sp.d[1].bhh = b_hh1_b;
        sp.d[1].cbuf = cb;
        sp.d[1].o = o1 + (long)tt * 256 + HN;
        sp.d[1].hstride = (long)TN * 256; sp.d[1].ostride = (long)TN * 256;
        sp.d[1].whoff = 192;
        lstm_mma<<<sgrid, sblk, SMEM_DYN>>>(sp);
    }

    // ---- layer 2 ----
    gemm_xp<<<ggrid, gblk, GSMEM>>>(o1, 256, w + 2 * WCFG, xp, 4);
    for (int t = 0; t < TN; ++t) {
        StepP sp;
        sp.first = (t == 0);
        sp.d[0].xp = xp + (long)t * 1024;
        sp.d[0].ah = t ? o2 + (long)(t - 1) * 256 : o2;
        sp.d[0].w = w + 2 * WCFG;
        sp.d[0].bih = b_ih2_f; sp.d[0].bhh = b_hh2_f;
        sp.d[0].cbuf = cf;
        sp.d[0].o = o2 + (long)t * 256;
        sp.d[0].hstride = (long)TN * 256; sp.d[0].ostride = (long)TN * 256;
        sp.d[0].whoff = 256;
        int tt = TN - 1 - t;
        sp.d[1].xp = xp + (long)tt * 1024 + 512;
        sp.d[1].ah = t ? o2 + (long)(tt + 1) * 256 + HN : o2;
        sp.d[1].w = w + 3 * WCFG;
        sp.d[1].bih = b_ih2_b; sp.d[1].bhh = b_hh2_b;
        sp.d[1].cbuf = cb;
        sp.d[1].o = o2 + (long)tt * 256 + HN;
        sp.d[1].hstride = (long)TN * 256; sp.d[1].ostride = (long)TN * 256;
        sp.d[1].whoff = 256;
        lstm_mma<<<sgrid, sblk, SMEM_DYN>>>(sp);
    }

    pool_kernel<<<(unsigned)(((long)BSZ * 512 + 255) / 256), 256>>>(o2, pooled);
    fc_kernel<<<BSZ / 64, 256>>>(pooled, fc1_w, fc1_b, fc2_w, fc2_b, (float*)d_out);
}

// round 17
// speedup vs baseline: 1.2595x; 1.2595x over previous
#include <cuda_runtime.h>
#include <cuda_fp16.h>
#include <cstdint>
#include <math.h>

#define BSZ 16384
#define TN  10
#define IN_ 184
#define HN  128
#define WST 384          // weight-cat row stride (fp16 elems)

// ------------------------- scratch (__device__ globals) -------------------------
__device__ __half g_x1[(size_t)BSZ * TN * 192];
__device__ __half g_o1[(size_t)BSZ * TN * 256];
__device__ __half g_o2[(size_t)BSZ * TN * 256];
__device__ __half g_w[(size_t)4 * 512 * WST];
__device__ float g_cf[(size_t)BSZ * HN];
__device__ float g_cb[(size_t)BSZ * HN];
__device__ float g_pooled[(size_t)BSZ * 512];

// ------------------------- small helpers -------------------------
__device__ __forceinline__ uint32_t smem_u32(const void* p) {
    uint32_t a;
    asm("{ .reg .u64 t; cvta.to.shared.u64 t, %1; cvt.u32.u64 %0, t; }" : "=r"(a) : "l"(p));
    return a;
}
__device__ __forceinline__ void ldsm_x4(uint32_t& r0, uint32_t& r1, uint32_t& r2, uint32_t& r3, uint32_t addr) {
    asm volatile("ldmatrix.sync.aligned.m8n8.x4.shared.b16 {%0,%1,%2,%3}, [%4];"
                 : "=r"(r0), "=r"(r1), "=r"(r2), "=r"(r3) : "r"(addr));
}
__device__ __forceinline__ void mma16816(float* d, const uint32_t* a, const uint32_t* b) {
    asm volatile("mma.sync.aligned.m16n8k16.row.col.f32.f16.f16.f32 "
                 "{%0,%1,%2,%3}, {%4,%5,%6,%7}, {%8,%9}, {%0,%1,%2,%3};"
                 : "+f"(d[0]), "+f"(d[1]), "+f"(d[2]), "+f"(d[3])
                 : "r"(a[0]), "r"(a[1]), "r"(a[2]), "r"(a[3]), "r"(b[0]), "r"(b[1]));
}
__device__ __forceinline__ void cpa16(uint32_t saddr, const void* gptr) {
    asm volatile("cp.async.cg.shared.global [%0], [%1], 16;" :: "r"(saddr), "l"(gptr));
}
__device__ __forceinline__ void cpa_commit() { asm volatile("cp.async.commit_group;"); }
__device__ __forceinline__ void cpa_wait1()  { asm volatile("cp.async.wait_group 1;"); }
__device__ __forceinline__ void cpa_wait0()  { asm volatile("cp.async.wait_group 0;"); }
__device__ __forceinline__ float ftanh(float x) {
    float e = __expf(2.f * x);
    return 1.f - 2.f / (e + 1.f);
}

// ------------------------- conversions -------------------------
__global__ void conv_x_kernel(const float* __restrict__ x, __half* __restrict__ xo) {
    long i = (long)blockIdx.x * blockDim.x + threadIdx.x;
    if (i >= (long)BSZ * TN * 192) return;
    int col = (int)(i % 192);
    long bt = i / 192;
    float v = (col < IN_) ? x[bt * IN_ + col] : 0.f;
    xo[i] = __float2half_rn(v);
}

__global__ void conv_w_kernel(const float* __restrict__ a0, const float* __restrict__ h0,
                              const float* __restrict__ a1, const float* __restrict__ h1,
                              const float* __restrict__ a2, const float* __restrict__ h2,
                              const float* __restrict__ a3, const float* __restrict__ h3,
                              __half* __restrict__ w) {
    long i = (long)blockIdx.x * blockDim.x + threadIdx.x;
    if (i >= (long)4 * 512 * WST) return;
    int col = (int)(i % WST);
    int r = (int)((i / WST) % 512);
    int cfg = (int)(i / ((long)512 * WST));
    const float* wih; const float* whh; int kx, hoff;
    switch (cfg) {
        case 0: wih = a0; whh = h0; kx = 184; hoff = 192; break;
        case 1: wih = a1; whh = h1; kx = 184; hoff = 192; break;
        case 2: wih = a2; whh = h2; kx = 256; hoff = 256; break;
        default: wih = a3; whh = h3; kx = 256; hoff = 256; break;
    }
    float v = 0.f;
    if (col < kx)                             v = wih[(long)r * kx + col];
    else if (col >= hoff && col < hoff + 128) v = whh[(long)r * 128 + (col - hoff)];
    w[i] = __float2half_rn(v);
}

// ------------------------- fused HMMA LSTM step -------------------------
// Block: 128 batch rows x 128 cols (32 units x 4 gates, col = 4*unit + gate).
// 256 threads = 8 warps in 2(m) x 4(n); warp tile 64 x 32. Pure fp16, 1 combo.
// 2-stage cp.async pipeline over 64-col K chunks.
struct DirP {
    const __half *ax;                 // x-part base (offset to this step's t)
    const __half *ah;                 // h-part base; unused if first
    const __half *w;                  // weight-cat cfg [512][WST]
    const float *bih, *bhh;
    float* cbuf;
    __half *o;
    long xstride, hstride, ostride;
    int xchunks, nchunks;             // in 64-col chunks
};
struct StepP { DirP d[2]; int first; };

#define LDA 72
#define T64 (128 * LDA)                  // elems per tile (A or W)
#define STG (2 * T64)                    // elems per stage
#define SMEM_DYN (2 * STG * 2 + 512)

__global__ __launch_bounds__(256, 2)
void lstm_mma(StepP sp)
{
    extern __shared__ char dyn[];
    float* sBias = (float*)(dyn + 2 * STG * 2);
    const uint32_t sb = smem_u32(dyn);

    const DirP& P = sp.d[blockIdx.z];
    const int first = sp.first;
    const int tid = threadIdx.x, lane = tid & 31, warp = tid >> 5;
    const int wm = warp >> 2, wn = warp & 3;          // warp grid 2(m) x 4(n)
    const int b0 = blockIdx.x * 128, n0 = blockIdx.y * 32;

    if (tid < 128) {
        int u = tid >> 2, g = tid & 3;
        int wr = g * 128 + n0 + u;
        sBias[tid] = P.bih[wr] + P.bhh[wr];
    }

    float acc[4][4][4];
#pragma unroll
    for (int i = 0; i < 4; ++i)
#pragma unroll
        for (int j = 0; j < 4; ++j)
#pragma unroll
            for (int k = 0; k < 4; ++k) acc[i][j][k] = 0.f;

    const int nc = first ? P.xchunks : P.nchunks;

    // per-thread load slots: 1024 granules per tile, 4 per thread
    const int lrow = tid >> 1;                        // A/W rows handled (2 gran each) x2 its
    const int lgc  = (tid & 1) * 8;                   // granule col base (x4 via it loop)

    auto load_chunk = [&](int c, int s) {
        const uint32_t st = sb + (uint32_t)s * STG * 2;
        const bool isx = (c < P.xchunks);
        const long acol = (long)(isx ? c : (c - P.xchunks)) * 64;
        const long astr = isx ? P.xstride : P.hstride;
        const __half* ab = isx ? P.ax : P.ah;
        const long wcol = (long)c * 64;
#pragma unroll
        for (int it = 0; it < 4; ++it) {
            int idx = tid + it * 256;                 // 0..1023
            int row = idx >> 3, gc = (idx & 7) * 8;
            cpa16(st + ((uint32_t)row * LDA + gc) * 2,
                  ab + (long)(b0 + row) * astr + acol + gc);
        }
#pragma unroll
        for (int it = 0; it < 4; ++it) {
            int idx = tid + it * 256;
            int cl = idx >> 3, gc = (idx & 7) * 8;
            int wr = (cl & 3) * 128 + n0 + (cl >> 2);
            cpa16(st + (T64 + (uint32_t)cl * LDA + gc) * 2,
                  P.w + (long)wr * WST + wcol + gc);
        }
        cpa_commit();
    };

    // ldmatrix lane-address components
    const int aRow = (lane & 15), aKo = (lane >> 4) * 8;
    const int bRow = (lane & 7);
    const int bKo  = ((lane >> 3) & 1) * 8;
    const int bNs  = ((lane >> 4) & 1) * 8;

    load_chunk(0, 0);

    for (int c = 0; c < nc; ++c) {
        const int cs = c & 1;
        if (c + 1 < nc) { load_chunk(c + 1, cs ^ 1); cpa_wait1(); }
        else            { cpa_wait0(); }
        __syncthreads();

        const uint32_t st = sb + (uint32_t)cs * STG * 2;
        const uint32_t uA = st, uW = st + T64 * 2;

#pragma unroll
        for (int kk = 0; kk < 4; ++kk) {
            const uint32_t aoff = ((uint32_t)(wm * 64 + aRow) * LDA + kk * 16 + aKo) * 2;
            uint32_t ah[4][4];
#pragma unroll
            for (int mi = 0; mi < 4; ++mi)
                ldsm_x4(ah[mi][0], ah[mi][1], ah[mi][2], ah[mi][3], uA + aoff + mi * 16 * LDA * 2);
#pragma unroll
            for (int np = 0; np < 2; ++np) {          // ni pairs {0,1}, {2,3}
                const uint32_t boff = ((uint32_t)(wn * 32 + np * 16 + bNs + bRow) * LDA + kk * 16 + bKo) * 2;
                uint32_t bw[4];
                ldsm_x4(bw[0], bw[1], bw[2], bw[3], uW + boff);
#pragma unroll
                for (int mi = 0; mi < 4; ++mi) {
                    mma16816(acc[mi][np * 2 + 0], ah[mi], bw + 0);
                    mma16816(acc[mi][np * 2 + 1], ah[mi], bw + 2);
                }
            }
        }
        __syncthreads();
    }

    // ---- epilogue: pair-exchange gates, LSTM pointwise, write h + c ----
    const bool odd = (lane & 1);
    const int rbase = lane >> 2;
    const int usub = (lane >> 1) & 1;
#pragma unroll
    for (int mi = 0; mi < 4; ++mi) {
#pragma unroll
        for (int ni = 0; ni < 4; ++ni) {
            float c0 = acc[mi][ni][0], c1 = acc[mi][ni][1], c2 = acc[mi][ni][2], c3 = acc[mi][ni][3];
            float s0 = __shfl_xor_sync(0xFFFFFFFFu, c0, 1);
            float s1 = __shfl_xor_sync(0xFFFFFFFFu, c1, 1);
            float s2 = __shfl_xor_sync(0xFFFFFFFFu, c2, 1);
            float s3 = __shfl_xor_sync(0xFFFFFFFFu, c3, 1);
            float vi, vf, vg, vo;
            int r;
            if (!odd) { vi = c0; vf = c1; vg = s0; vo = s1; r = rbase; }
            else      { vi = s2; vf = s3; vg = c2; vo = c3; r = rbase + 8; }
            const int ul = ((wn * 32 + ni * 8) >> 2) + usub;      // unit local 0..31
            const float4 bb = *(const float4*)&sBias[4 * ul];
            vi += bb.x; vf += bb.y; vg += bb.z; vo += bb.w;
            float ig = 1.f / (1.f + __expf(-vi));
            float fg = 1.f / (1.f + __expf(-vf));
            float gg = ftanh(vg);
            float og = 1.f / (1.f + __expf(-vo));
            const long b = b0 + wm * 64 + mi * 16 + r;
            const int gu = n0 + ul;
            float cp = first ? 0.f : P.cbuf[b * HN + gu];
            float cn = fg * cp + ig * gg;
            P.cbuf[b * HN + gu] = cn;
            float h = og * ftanh(cn);
            P.o[b * P.ostride + gu] = __float2half_rn(h);
        }
    }
}

// ------------------------- temporal max-pool -------------------------
__global__ void pool_kernel(const __half* __restrict__ o2, float* __restrict__ pooled)
{
    long idx = (long)blockIdx.x * blockDim.x + threadIdx.x;
    if (idx >= (long)BSZ * 512) return;
    int b = (int)(idx >> 9);
    int col = (int)(idx & 511);
    int h = col >> 1, p = col & 1;
    long base = ((long)b * TN + p * 5) * 256 + h;
    float m = -1e30f;
#pragma unroll
    for (int s = 0; s < 5; ++s)
        m = fmaxf(m, __half2float(o2[base + (long)s * 256]));
    pooled[idx] = m;
}

// ------------------------- fused FC1(relu)+FC2 -------------------------
__global__ __launch_bounds__(256)
void fc_kernel(const float* __restrict__ pooled,
               const float* __restrict__ w1, const float* __restrict__ b1,
               const float* __restrict__ w2, const float* __restrict__ b2,
               float* __restrict__ outp)
{
    __shared__ float S[64 * 65 + 64 * 64];
    float (*Ws)[65] = (float (*)[65])S;
    float (*Ps)[64] = (float (*)[64])(S + 64 * 65);

    const int tid = threadIdx.x;
    const int b0 = blockIdx.x * 64;
    const int o  = tid & 63;
    const int tg = tid >> 6;

    float acc[16];
#pragma unroll
    for (int r = 0; r < 16; ++r) acc[r] = 0.f;

    for (int kt = 0; kt < 512; kt += 64) {
        for (int e = tid; e < 64 * 64; e += 256) {
            int oo = e >> 6, k = e & 63;
            Ws[k][oo] = w1[(long)oo * 512 + kt + k];
            Ps[oo][k] = pooled[(long)(b0 + oo) * 512 + kt + k];
        }
        __syncthreads();
#pragma unroll 4
        for (int k = 0; k < 64; ++k) {
            float w = Ws[k][o];
#pragma unroll
            for (int r = 0; r < 16; ++r)
                acc[r] = fmaf(Ps[tg * 16 + r][k], w, acc[r]);
        }
        __syncthreads();
    }
    float (*H1)[65] = (float (*)[65])S;
    float bias1 = b1[o];
#pragma unroll
    for (int r = 0; r < 16; ++r)
        H1[tg * 16 + r][o] = fmaxf(acc[r] + bias1, 0.f);
    __syncthreads();
    if (tid < 64) {
        float a2 = b2[0];
#pragma unroll
        for (int oo = 0; oo < 64; ++oo) a2 = fmaf(H1[tid][oo], w2[oo], a2);
        outp[b0 + tid] = a2;
    }
}

// ------------------------- host launcher -------------------------
extern "C" void kernel_launch(void* const* d_in, const int* in_sizes, int n_in,
                              void* d_out, int out_size)
{
    const float* x       = (const float*)d_in[0];
    const float* w_ih1_f = (const float*)d_in[1];
    const float* w_hh1_f = (const float*)d_in[2];
    const float* b_ih1_f = (const float*)d_in[3];
    const float* b_hh1_f = (const float*)d_in[4];
    const float* w_ih1_b = (const float*)d_in[5];
    const float* w_hh1_b = (const float*)d_in[6];
    const float* b_ih1_b = (const float*)d_in[7];
    const float* b_hh1_b = (const float*)d_in[8];
    const float* w_ih2_f = (const float*)d_in[9];
    const float* w_hh2_f = (const float*)d_in[10];
    const float* b_ih2_f = (const float*)d_in[11];
    const float* b_hh2_f = (const float*)d_in[12];
    const float* w_ih2_b = (const float*)d_in[13];
    const float* w_hh2_b = (const float*)d_in[14];
    const float* b_ih2_b = (const float*)d_in[15];
    const float* b_hh2_b = (const float*)d_in[16];
    const float* fc1_w   = (const float*)d_in[17];
    const float* fc1_b   = (const float*)d_in[18];
    const float* fc2_w   = (const float*)d_in[19];
    const float* fc2_b   = (const float*)d_in[20];

    __half *x1, *o1, *o2, *w;
    float *cf, *cb, *pooled;
    cudaGetSymbolAddress((void**)&x1, g_x1);
    cudaGetSymbolAddress((void**)&o1, g_o1);
    cudaGetSymbolAddress((void**)&o2, g_o2);
    cudaGetSymbolAddress((void**)&w, g_w);
    cudaGetSymbolAddress((void**)&cf, g_cf);
    cudaGetSymbolAddress((void**)&cb, g_cb);
    cudaGetSymbolAddress((void**)&pooled, g_pooled);

    cudaFuncSetAttribute(lstm_mma, cudaFuncAttributeMaxDynamicSharedMemorySize, SMEM_DYN);

    {
        long n = (long)BSZ * TN * 192;
        conv_x_kernel<<<(unsigned)((n + 255) / 256), 256>>>(x, x1);
        long m = (long)4 * 512 * WST;
        conv_w_kernel<<<(unsigned)((m + 255) / 256), 256>>>(
            w_ih1_f, w_hh1_f, w_ih1_b, w_hh1_b, w_ih2_f, w_hh2_f, w_ih2_b, w_hh2_b, w);
    }

    dim3 grid(BSZ / 128, 4, 2), blk(256);
    const long WCFG = (long)512 * WST;

    // ---- layer 1 ---- (x: 3 chunks of 64, h: 2 chunks)
    for (int t = 0; t < TN; ++t) {
        StepP sp;
        sp.first = (t == 0);
        sp.d[0].ax = x1 + (long)t * 192;
        sp.d[0].ah = t ? o1 + (long)(t - 1) * 256 : o1;
        sp.d[0].w = w + 0 * WCFG;
        sp.d[0].bih = b_ih1_f; sp.d[0].bhh = b_hh1_f;
        sp.d[0].cbuf = cf;
        sp.d[0].o = o1 + (long)t * 256;
        sp.d[0].xstride = (long)TN * 192; sp.d[0].hstride = (long)TN * 256; sp.d[0].ostride = (long)TN * 256;
        sp.d[0].xchunks = 3; sp.d[0].nchunks = 5;
        int tt = TN - 1 - t;
        sp.d[1].ax = x1 + (long)tt * 192;
        sp.d[1].ah = t ? o1 + (long)(tt + 1) * 256 + HN : o1;
        sp.d[1].w = w + 1 * WCFG;
        sp.d[1].bih = b_ih1_b; sp.d[1].bhh = b_hh1_b;
        sp.d[1].cbuf = cb;
        sp.d[1].o = o1 + (long)tt * 256 + HN;
        sp.d[1].xstride = (long)TN * 192; sp.d[1].hstride = (long)TN * 256; sp.d[1].ostride = (long)TN * 256;
        sp.d[1].xchunks = 3; sp.d[1].nchunks = 5;
        lstm_mma<<<grid, blk, SMEM_DYN>>>(sp);
    }

    // ---- layer 2 ---- (x: 4 chunks, h: 2 chunks)
    for (int t = 0; t < TN; ++t) {
        StepP sp;
        sp.first = (t == 0);
        sp.d[0].ax = o1 + (long)t * 256;
        sp.d[0].ah = t ? o2 + (long)(t - 1) * 256 : o2;
        sp.d[0].w = w + 2 * WCFG;
        sp.d[0].bih = b_ih2_f; sp.d[0].bhh = b_hh2_f;
        sp.d[0].cbuf = cf;
        sp.d[0].o = o2 + (long)t * 256;
        sp.d[0].xstride = (long)TN * 256; sp.d[0].hstride = (long)TN * 256; sp.d[0].ostride = (long)TN * 256;
        sp.d[0].xchunks = 4; sp.d[0].nchunks = 6;
        int tt = TN - 1 - t;
        sp.d[1].ax = o1 + (long)tt * 256;
        sp.d[1].ah = t ? o2 + (long)(tt + 1) * 256 + HN : o2;
        sp.d[1].w = w + 3 * WCFG;
        sp.d[1].bih = b_ih2_b; sp.d[1].bhh = b_hh2_b;
        sp.d[1].cbuf = cb;
        sp.d[1].o = o2 + (long)tt * 256 + HN;
        sp.d[1].xstride = (long)TN * 256; sp.d[1].hstride = (long)TN * 256; sp.d[1].ostride = (long)TN * 256;
        sp.d[1].xchunks = 4; sp.d[1].nchunks = 6;
        lstm_mma<<<grid, blk, SMEM_DYN>>>(sp);
    }

    pool_kernel<<<(unsigned)(((long)BSZ * 512 + 255) / 256), 256>>>(o2, pooled);
    fc_kernel<<<BSZ / 64, 256>>>(pooled, fc1_w, fc1_b, fc2_w, fc2_b, (float*)d_out);
}